// round 12
// baseline (speedup 1.0000x reference)
#include <cuda_runtime.h>
#include <math.h>

#define N_NODES 20000
#define N_EDGES 150000
#define FEAT    64
#define HEADS   8
#define N_RBF   20
#define HF      512          // HEADS*FEAT
#define NCOLS   1024         // Q(512) | K(512)
#define CUTOFF  5.0f
#define PI_F    3.14159265358979f

// Scratch: per-node Q and K projections, [node][ Q(0..511) | K(512..1023) ]
__device__ float g_QK[(size_t)N_NODES * NCOLS];

// ---------------------------------------------------------------------------
// Packed f32x2 helpers (Blackwell FFMA2 — only reachable via PTX fma.rn.f32x2)
// ---------------------------------------------------------------------------
__device__ __forceinline__ unsigned long long ffma2(unsigned long long a,
                                                    unsigned long long b,
                                                    unsigned long long c) {
    unsigned long long d;
    asm("fma.rn.f32x2 %0, %1, %2, %3;" : "=l"(d) : "l"(a), "l"(b), "l"(c));
    return d;
}

__device__ __forceinline__ unsigned long long pack2(float lo, float hi) {
    unsigned long long r;
    asm("mov.b64 %0, {%1, %2};" : "=l"(r) : "f"(lo), "f"(hi));
    return r;
}

__device__ __forceinline__ float2 unpack2(unsigned long long v) {
    float2 r;
    asm("mov.b64 {%0, %1}, %2;" : "=f"(r.x), "=f"(r.y) : "l"(v));
    return r;
}

// ---------------------------------------------------------------------------
// Kernel 1: fused Q|K projection GEMM, FFMA2 microtile (R8 measured-best).
// ---------------------------------------------------------------------------
#define BM 128
#define BN 128
#define BK 32
#define LDP 132   // padded leading dim for transposed tiles (conflict-free)

__global__ __launch_bounds__(256)
void qk_gemm_kernel(const float* __restrict__ x_i,
                    const float* __restrict__ W_q, const float* __restrict__ b_q,
                    const float* __restrict__ W_k, const float* __restrict__ b_k)
{
    __shared__ float A_t[BK][LDP];   // A_t[k][m]
    __shared__ float B_t[BK][LDP];   // B_t[k][n]

    const int tid  = threadIdx.x;
    const int row0 = blockIdx.x * BM;
    const int col0 = blockIdx.y * BN;

    const float* Bsrc;
    const float* bias_src;
    if (col0 < HF) { Bsrc = W_q + (size_t)col0 * FEAT;        bias_src = b_q + col0; }
    else           { Bsrc = W_k + (size_t)(col0 - HF) * FEAT; bias_src = b_k + (col0 - HF); }

    const int tx = tid & 15;     // 0..15 -> col group
    const int ty = tid >> 4;     // 0..15 -> row group

    // acc2[i][j2] = (acc[i][2*j2], acc[i][2*j2+1]) packed
    unsigned long long acc2[8][4];
    const unsigned long long zz = pack2(0.f, 0.f);
    #pragma unroll
    for (int i = 0; i < 8; i++)
        #pragma unroll
        for (int j = 0; j < 4; j++) acc2[i][j] = zz;

    for (int kk = 0; kk < FEAT; kk += BK) {
        #pragma unroll
        for (int r = 0; r < 4; r++) {
            int f  = tid + 256 * r;      // 0..1023
            int ml = f >> 3;             // local row 0..127
            int kg = f & 7;              // float4 group within BK
            int m  = row0 + ml;
            float4 va = make_float4(0.f, 0.f, 0.f, 0.f);
            if (m < N_NODES)
                va = *(const float4*)(x_i + (size_t)m * FEAT + kk + kg * 4);
            A_t[kg * 4 + 0][ml] = va.x;
            A_t[kg * 4 + 1][ml] = va.y;
            A_t[kg * 4 + 2][ml] = va.z;
            A_t[kg * 4 + 3][ml] = va.w;
            float4 vb = *(const float4*)(Bsrc + (size_t)ml * FEAT + kk + kg * 4);
            B_t[kg * 4 + 0][ml] = vb.x;
            B_t[kg * 4 + 1][ml] = vb.y;
            B_t[kg * 4 + 2][ml] = vb.z;
            B_t[kg * 4 + 3][ml] = vb.w;
        }
        __syncthreads();

        #pragma unroll
        for (int k = 0; k < BK; k++) {
            float a[8];
            *(float4*)(a)     = *(const float4*)&A_t[k][ty * 8];
            *(float4*)(a + 4) = *(const float4*)&A_t[k][ty * 8 + 4];
            ulonglong2 bv0 = *(const ulonglong2*)&B_t[k][tx * 8];
            ulonglong2 bv1 = *(const ulonglong2*)&B_t[k][tx * 8 + 4];
            unsigned long long bb[4] = {bv0.x, bv0.y, bv1.x, bv1.y};
            #pragma unroll
            for (int i = 0; i < 8; i++) {
                const unsigned long long ad = pack2(a[i], a[i]);
                #pragma unroll
                for (int j = 0; j < 4; j++)
                    acc2[i][j] = ffma2(bb[j], ad, acc2[i][j]);
            }
        }
        __syncthreads();
    }

    float bias[8];
    #pragma unroll
    for (int j = 0; j < 8; j++) bias[j] = bias_src[tx * 8 + j];

    #pragma unroll
    for (int i = 0; i < 8; i++) {
        int m = row0 + ty * 8 + i;
        if (m < N_NODES) {
            float* dst = &g_QK[(size_t)m * NCOLS + col0 + tx * 8];
            float2 c0 = unpack2(acc2[i][0]), c1 = unpack2(acc2[i][1]);
            float2 c2 = unpack2(acc2[i][2]), c3 = unpack2(acc2[i][3]);
            float4 o0, o1;
            o0.x = c0.x + bias[0]; o0.y = c0.y + bias[1];
            o0.z = c1.x + bias[2]; o0.w = c1.y + bias[3];
            o1.x = c2.x + bias[4]; o1.y = c2.y + bias[5];
            o1.z = c3.x + bias[6]; o1.w = c3.y + bias[7];
            *(float4*)(dst)     = o0;
            *(float4*)(dst + 4) = o1;
        }
    }
}

// ---------------------------------------------------------------------------
// Kernel 2: fused edge kernel. 256 threads, warp == head, 2 cols/thread.
// Batched MLP pipeline: 8-edge q/k register batches, double-buffered — while
// batch X computes, batch X+1's nbr + q/k loads are in flight (cross-group).
// 2 CTAs/SM (regs); ef double-buffered in smem; octet butterfly + batched
// finish unchanged.
// ---------------------------------------------------------------------------
#define EPB 16                    // edges per block iteration
#define HB  8                     // half-batch (edges per q/k register batch)
#define NGROUPS (N_EDGES / EPB)   // 9375, exact
#define GRID2   296               // 148 SMs * 2 CTAs
#define TPB2    256

__device__ __forceinline__ float silu_f(float x) {
    return __fdividef(x, 1.f + __expf(-x));
}

__global__ __launch_bounds__(TPB2, 2)
void edge_kernel(const float* __restrict__ dist,
                 const int*   __restrict__ nbrs,
                 const float* __restrict__ W_dk,
                 const float* __restrict__ b_dk,
                 float*       __restrict__ out)
{
    __shared__ alignas(16) float ef_s[2][EPB][24];      // 20 RBF values, padded
    __shared__ alignas(16) float oct_s[HEADS][EPB][4];  // octet partials per warp

    const int tid  = threadIdx.x;
    const int lane = tid & 31;
    const int warp = tid >> 5;           // == head
    const int c0   = warp * 64 + lane * 2;

    const float* __restrict__ gQ = g_QK + c0;
    const float* __restrict__ gK = g_QK + HF + c0;

    // W_dk rows for cols c0, c0+1 as r-packed f32x2 pairs (kept in registers)
    const ulonglong2* wpA = (const ulonglong2*)(W_dk + (size_t)c0 * N_RBF);
    const ulonglong2* wpB = (const ulonglong2*)(W_dk + (size_t)(c0 + 1) * N_RBF);
    const ulonglong2 wa0 = wpA[0], wa1 = wpA[1], wa2 = wpA[2], wa3 = wpA[3], wa4 = wpA[4];
    const ulonglong2 wb0 = wpB[0], wb1 = wpB[1], wb2 = wpB[2], wb3 = wpB[3], wb4 = wpB[4];
    const unsigned long long aA0 = pack2(b_dk[c0], 0.f);
    const unsigned long long aB0 = pack2(b_dk[c0 + 1], 0.f);
    const unsigned long long zz  = pack2(0.f, 0.f);

    // RBF fill for group g into ef buffer buf (idx no longer staged in smem)
    auto fill = [&](int g, int buf) {
        const int e0 = g * EPB;
        #pragma unroll
        for (int v = tid; v < EPB * N_RBF; v += TPB2) {
            int el = v / N_RBF, r = v % N_RBF;
            float d   = dist[e0 + el];
            float t   = PI_F * d * (1.0f / CUTOFF);
            float env = (d < CUTOFF) ? 0.5f * (__cosf(t) + 1.f) : 0.f;
            ef_s[buf][el][r] = __sinf((float)(r + 1) * t) * __fdividef(env, d);
        }
    };

    // broadcast LDG of neighbor pairs for a half-batch
    auto load_nbrs = [&](int e_base, int2* nb) {
        #pragma unroll
        for (int i = 0; i < HB; i++)
            nb[i] = ((const int2*)nbrs)[e_base + i];
    };
    auto load_qk = [&](const int2* nb, float2* q, float2* k) {
        #pragma unroll
        for (int i = 0; i < HB; i++) {
            q[i] = *(const float2*)(gQ + (size_t)nb[i].x * NCOLS);
            k[i] = *(const float2*)(gK + (size_t)nb[i].y * NCOLS);
        }
    };

    // per-edge compute: dk dot, triple product, octet butterfly, park partial
    auto compute_edge = [&](int buf, int el, float2 qc, float2 kc) {
        const ulonglong2* efp = (const ulonglong2*)&ef_s[buf][el][0];
        ulonglong2 e0v = efp[0], e1v = efp[1], e2v = efp[2], e3v = efp[3], e4v = efp[4];

        unsigned long long aA1 = aA0, aA2 = zz;   // column c0
        unsigned long long aB1 = aB0, aB2 = zz;   // column c0+1
        aA1 = ffma2(e0v.x, wa0.x, aA1);  aA2 = ffma2(e0v.y, wa0.y, aA2);
        aB1 = ffma2(e0v.x, wb0.x, aB1);  aB2 = ffma2(e0v.y, wb0.y, aB2);
        aA1 = ffma2(e1v.x, wa1.x, aA1);  aA2 = ffma2(e1v.y, wa1.y, aA2);
        aB1 = ffma2(e1v.x, wb1.x, aB1);  aB2 = ffma2(e1v.y, wb1.y, aB2);
        aA1 = ffma2(e2v.x, wa2.x, aA1);  aA2 = ffma2(e2v.y, wa2.y, aA2);
        aB1 = ffma2(e2v.x, wb2.x, aB1);  aB2 = ffma2(e2v.y, wb2.y, aB2);
        aA1 = ffma2(e3v.x, wa3.x, aA1);  aA2 = ffma2(e3v.y, wa3.y, aA2);
        aB1 = ffma2(e3v.x, wb3.x, aB1);  aB2 = ffma2(e3v.y, wb3.y, aB2);
        aA1 = ffma2(e4v.x, wa4.x, aA1);  aA2 = ffma2(e4v.y, wa4.y, aA2);
        aB1 = ffma2(e4v.x, wb4.x, aB1);  aB2 = ffma2(e4v.y, wb4.y, aB2);

        float2 fa1 = unpack2(aA1), fa2 = unpack2(aA2);
        float2 fb1 = unpack2(aB1), fb2 = unpack2(aB2);
        float sA = (fa1.x + fa1.y) + (fa2.x + fa2.y);
        float sB = (fb1.x + fb1.y) + (fb2.x + fb2.y);

        float p = qc.x * kc.x * silu_f(sA);
        p = fmaf(qc.y * kc.y, silu_f(sB), p);

        p += __shfl_xor_sync(0xffffffffu, p, 4);
        p += __shfl_xor_sync(0xffffffffu, p, 2);
        p += __shfl_xor_sync(0xffffffffu, p, 1);
        if ((lane & 7) == 0) oct_s[warp][el][lane >> 3] = p;
    };

    int g   = blockIdx.x;
    int buf = 0;
    fill(g, 0);

    float2 qA[HB], kA[HB], qB[HB], kB[HB];
    int2   nb[HB];
    load_nbrs(g * EPB, nb);
    load_qk(nb, qA, kA);                 // batch A of first group in flight

    for (; g < NGROUPS; g += GRID2) {
        const int gn = g + GRID2;
        __syncthreads();                 // ef_s[buf] ready for everyone
        if (gn < NGROUPS) fill(gn, buf ^ 1);

        const int e0 = g * EPB;

        // ---- batch A compute; batch B loads go in flight
        load_nbrs(e0 + HB, nb);
        compute_edge(buf, 0, qA[0], kA[0]);
        compute_edge(buf, 1, qA[1], kA[1]);
        load_qk(nb, qB, kB);
        compute_edge(buf, 2, qA[2], kA[2]);
        compute_edge(buf, 3, qA[3], kA[3]);
        compute_edge(buf, 4, qA[4], kA[4]);
        compute_edge(buf, 5, qA[5], kA[5]);
        compute_edge(buf, 6, qA[6], kA[6]);
        compute_edge(buf, 7, qA[7], kA[7]);

        // ---- batch B compute; NEXT group's batch A loads go in flight
        if (gn < NGROUPS) load_nbrs(gn * EPB, nb);
        compute_edge(buf, 8,  qB[0], kB[0]);
        compute_edge(buf, 9,  qB[1], kB[1]);
        if (gn < NGROUPS) load_qk(nb, qA, kA);
        compute_edge(buf, 10, qB[2], kB[2]);
        compute_edge(buf, 11, qB[3], kB[3]);
        compute_edge(buf, 12, qB[4], kB[4]);
        compute_edge(buf, 13, qB[5], kB[5]);
        compute_edge(buf, 14, qB[6], kB[6]);
        compute_edge(buf, 15, qB[7], kB[7]);

        __syncwarp();
        // ---- finish: lanes 0..15 each close one edge (batched, coalesced)
        if (lane < EPB) {
            const float4 pv = *(const float4*)&oct_s[warp][lane][0];
            float s = (pv.x + pv.y) + (pv.z + pv.w);
            out[(size_t)(e0 + lane) * HEADS + warp] = silu_f(s);
        }
        __syncwarp();
        buf ^= 1;
    }
}

// ---------------------------------------------------------------------------
extern "C" void kernel_launch(void* const* d_in, const int* in_sizes, int n_in,
                              void* d_out, int out_size)
{
    const float* dist = (const float*)d_in[0];
    const int*   nbrs = (const int*)  d_in[1];
    const float* x_i  = (const float*)d_in[2];
    const float* W_q  = (const float*)d_in[3];
    const float* b_q  = (const float*)d_in[4];
    const float* W_k  = (const float*)d_in[5];
    const float* b_k  = (const float*)d_in[6];
    const float* W_dk = (const float*)d_in[7];
    const float* b_dk = (const float*)d_in[8];
    float* out = (float*)d_out;

    dim3 g1((N_NODES + BM - 1) / BM, NCOLS / BN);   // 157 x 8
    qk_gemm_kernel<<<g1, 256>>>(x_i, W_q, b_q, W_k, b_k);

    edge_kernel<<<GRID2, TPB2>>>(dist, nbrs, W_dk, b_dk, out);
}

// round 14
// speedup vs baseline: 1.0746x; 1.0746x over previous
#include <cuda_runtime.h>
#include <math.h>

#define N_NODES 20000
#define N_EDGES 150000
#define FEAT    64
#define HEADS   8
#define N_RBF   20
#define HF      512          // HEADS*FEAT
#define NCOLS   1024         // Q(512) | K(512)
#define CUTOFF  5.0f
#define PI_F    3.14159265358979f

// Scratch: per-node Q and K projections, [node][ Q(0..511) | K(512..1023) ]
__device__ float g_QK[(size_t)N_NODES * NCOLS];

// ---------------------------------------------------------------------------
// Packed f32x2 helpers (Blackwell FFMA2 — only reachable via PTX fma.rn.f32x2)
// ---------------------------------------------------------------------------
__device__ __forceinline__ unsigned long long ffma2(unsigned long long a,
                                                    unsigned long long b,
                                                    unsigned long long c) {
    unsigned long long d;
    asm("fma.rn.f32x2 %0, %1, %2, %3;" : "=l"(d) : "l"(a), "l"(b), "l"(c));
    return d;
}

__device__ __forceinline__ unsigned long long pack2(float lo, float hi) {
    unsigned long long r;
    asm("mov.b64 %0, {%1, %2};" : "=l"(r) : "f"(lo), "f"(hi));
    return r;
}

__device__ __forceinline__ float2 unpack2(unsigned long long v) {
    float2 r;
    asm("mov.b64 {%0, %1}, %2;" : "=f"(r.x), "=f"(r.y) : "l"(v));
    return r;
}

// ---------------------------------------------------------------------------
// Kernel 1: fused Q|K projection GEMM, FFMA2 microtile (R8 measured-best).
// ---------------------------------------------------------------------------
#define BM 128
#define BN 128
#define BK 32
#define LDP 132   // padded leading dim for transposed tiles (conflict-free)

__global__ __launch_bounds__(256)
void qk_gemm_kernel(const float* __restrict__ x_i,
                    const float* __restrict__ W_q, const float* __restrict__ b_q,
                    const float* __restrict__ W_k, const float* __restrict__ b_k)
{
    __shared__ float A_t[BK][LDP];   // A_t[k][m]
    __shared__ float B_t[BK][LDP];   // B_t[k][n]

    const int tid  = threadIdx.x;
    const int row0 = blockIdx.x * BM;
    const int col0 = blockIdx.y * BN;

    const float* Bsrc;
    const float* bias_src;
    if (col0 < HF) { Bsrc = W_q + (size_t)col0 * FEAT;        bias_src = b_q + col0; }
    else           { Bsrc = W_k + (size_t)(col0 - HF) * FEAT; bias_src = b_k + (col0 - HF); }

    const int tx = tid & 15;     // 0..15 -> col group
    const int ty = tid >> 4;     // 0..15 -> row group

    // acc2[i][j2] = (acc[i][2*j2], acc[i][2*j2+1]) packed
    unsigned long long acc2[8][4];
    const unsigned long long zz = pack2(0.f, 0.f);
    #pragma unroll
    for (int i = 0; i < 8; i++)
        #pragma unroll
        for (int j = 0; j < 4; j++) acc2[i][j] = zz;

    for (int kk = 0; kk < FEAT; kk += BK) {
        #pragma unroll
        for (int r = 0; r < 4; r++) {
            int f  = tid + 256 * r;      // 0..1023
            int ml = f >> 3;             // local row 0..127
            int kg = f & 7;              // float4 group within BK
            int m  = row0 + ml;
            float4 va = make_float4(0.f, 0.f, 0.f, 0.f);
            if (m < N_NODES)
                va = *(const float4*)(x_i + (size_t)m * FEAT + kk + kg * 4);
            A_t[kg * 4 + 0][ml] = va.x;
            A_t[kg * 4 + 1][ml] = va.y;
            A_t[kg * 4 + 2][ml] = va.z;
            A_t[kg * 4 + 3][ml] = va.w;
            float4 vb = *(const float4*)(Bsrc + (size_t)ml * FEAT + kk + kg * 4);
            B_t[kg * 4 + 0][ml] = vb.x;
            B_t[kg * 4 + 1][ml] = vb.y;
            B_t[kg * 4 + 2][ml] = vb.z;
            B_t[kg * 4 + 3][ml] = vb.w;
        }
        __syncthreads();

        #pragma unroll
        for (int k = 0; k < BK; k++) {
            float a[8];
            *(float4*)(a)     = *(const float4*)&A_t[k][ty * 8];
            *(float4*)(a + 4) = *(const float4*)&A_t[k][ty * 8 + 4];
            ulonglong2 bv0 = *(const ulonglong2*)&B_t[k][tx * 8];
            ulonglong2 bv1 = *(const ulonglong2*)&B_t[k][tx * 8 + 4];
            unsigned long long bb[4] = {bv0.x, bv0.y, bv1.x, bv1.y};
            #pragma unroll
            for (int i = 0; i < 8; i++) {
                const unsigned long long ad = pack2(a[i], a[i]);
                #pragma unroll
                for (int j = 0; j < 4; j++)
                    acc2[i][j] = ffma2(bb[j], ad, acc2[i][j]);
            }
        }
        __syncthreads();
    }

    float bias[8];
    #pragma unroll
    for (int j = 0; j < 8; j++) bias[j] = bias_src[tx * 8 + j];

    #pragma unroll
    for (int i = 0; i < 8; i++) {
        int m = row0 + ty * 8 + i;
        if (m < N_NODES) {
            float* dst = &g_QK[(size_t)m * NCOLS + col0 + tx * 8];
            float2 c0 = unpack2(acc2[i][0]), c1 = unpack2(acc2[i][1]);
            float2 c2 = unpack2(acc2[i][2]), c3 = unpack2(acc2[i][3]);
            float4 o0, o1;
            o0.x = c0.x + bias[0]; o0.y = c0.y + bias[1];
            o0.z = c1.x + bias[2]; o0.w = c1.y + bias[3];
            o1.x = c2.x + bias[4]; o1.y = c2.y + bias[5];
            o1.z = c3.x + bias[6]; o1.w = c3.y + bias[7];
            *(float4*)(dst)     = o0;
            *(float4*)(dst + 4) = o1;
        }
    }
}

// ---------------------------------------------------------------------------
// Kernel 2: fused edge kernel — TLP variant. 256 threads, warp == head,
// 2 cols/thread, 4 CTAs/SM (<=64 regs target). No explicit q/k rotation
// (dk-dot is independent of q/k, so the gathers hoist naturally); 2
// accumulator chains; octet butterfly + batched finish per 16-edge group.
// ---------------------------------------------------------------------------
#define EPB 16                    // edges per block iteration
#define NGROUPS (N_EDGES / EPB)   // 9375, exact
#define GRID2   592               // 148 SMs * 4 CTAs
#define TPB2    256

__device__ __forceinline__ float silu_f(float x) {
    return __fdividef(x, 1.f + __expf(-x));
}

__global__ __launch_bounds__(TPB2, 4)
void edge_kernel(const float* __restrict__ dist,
                 const int*   __restrict__ nbrs,
                 const float* __restrict__ W_dk,
                 const float* __restrict__ b_dk,
                 float*       __restrict__ out)
{
    __shared__ alignas(16) float ef_s[2][EPB][24];   // 20 RBF values, padded row
    __shared__ int2 idx_s[2][EPB];
    __shared__ alignas(16) float oct_s[HEADS][EPB][4];  // octet partials per warp

    const int tid  = threadIdx.x;
    const int lane = tid & 31;
    const int warp = tid >> 5;           // == head
    const int c0   = warp * 64 + lane * 2;

    // Base pointers with the column offset folded in once
    const float* __restrict__ gQ = g_QK + c0;
    const float* __restrict__ gK = g_QK + HF + c0;

    // W_dk rows for cols c0 and c0+1 (each 20 floats, 80B => 16B aligned),
    // as r-packed f32x2 pairs: 10 pairs per column (kept in registers).
    const ulonglong2* wpA = (const ulonglong2*)(W_dk + (size_t)c0 * N_RBF);
    const ulonglong2* wpB = (const ulonglong2*)(W_dk + (size_t)(c0 + 1) * N_RBF);
    const ulonglong2 wa0 = wpA[0], wa1 = wpA[1], wa2 = wpA[2], wa3 = wpA[3], wa4 = wpA[4];
    const ulonglong2 wb0 = wpB[0], wb1 = wpB[1], wb2 = wpB[2], wb3 = wpB[3], wb4 = wpB[4];
    const unsigned long long aA0 = pack2(b_dk[c0], 0.f);
    const unsigned long long aB0 = pack2(b_dk[c0 + 1], 0.f);

    // stage-1 fill for group g into buffer buf
    auto fill = [&](int g, int buf) {
        const int e0 = g * EPB;
        #pragma unroll
        for (int v = tid; v < EPB * N_RBF; v += TPB2) {
            int el = v / N_RBF, r = v % N_RBF;
            float d   = dist[e0 + el];
            float t   = PI_F * d * (1.0f / CUTOFF);
            float env = (d < CUTOFF) ? 0.5f * (__cosf(t) + 1.f) : 0.f;
            ef_s[buf][el][r] = __sinf((float)(r + 1) * t) * __fdividef(env, d);
        }
        if (tid < EPB)
            idx_s[buf][tid] = ((const int2*)nbrs)[e0 + tid];
    };

    int g = blockIdx.x;
    fill(g, 0);
    int buf = 0;

    for (; g < NGROUPS; g += GRID2) {
        __syncthreads();                 // buf ready for everyone
        const int gn = g + GRID2;
        if (gn < NGROUPS) fill(gn, buf ^ 1);   // prefetch next group's RBF

        const int e0 = g * EPB;

        #pragma unroll 2
        for (int el = 0; el < EPB; el++) {
            int2 nn = idx_s[buf][el];
            // q/k gathers issue here; the dk-dot below is independent of them,
            // so ~35 instructions of latency cover happens without rotation.
            float2 qc = *(const float2*)(gQ + (size_t)nn.x * NCOLS);
            float2 kc = *(const float2*)(gK + (size_t)nn.y * NCOLS);

            const ulonglong2* efp = (const ulonglong2*)&ef_s[buf][el][0];
            ulonglong2 e0v = efp[0], e1v = efp[1], e2v = efp[2], e3v = efp[3], e4v = efp[4];

            // two chains, one per column (10 dependent FFMA2 each, interleaved)
            unsigned long long aA = aA0, aB = aB0;
            aA = ffma2(e0v.x, wa0.x, aA);  aB = ffma2(e0v.x, wb0.x, aB);
            aA = ffma2(e0v.y, wa0.y, aA);  aB = ffma2(e0v.y, wb0.y, aB);
            aA = ffma2(e1v.x, wa1.x, aA);  aB = ffma2(e1v.x, wb1.x, aB);
            aA = ffma2(e1v.y, wa1.y, aA);  aB = ffma2(e1v.y, wb1.y, aB);
            aA = ffma2(e2v.x, wa2.x, aA);  aB = ffma2(e2v.x, wb2.x, aB);
            aA = ffma2(e2v.y, wa2.y, aA);  aB = ffma2(e2v.y, wb2.y, aB);
            aA = ffma2(e3v.x, wa3.x, aA);  aB = ffma2(e3v.x, wb3.x, aB);
            aA = ffma2(e3v.y, wa3.y, aA);  aB = ffma2(e3v.y, wb3.y, aB);
            aA = ffma2(e4v.x, wa4.x, aA);  aB = ffma2(e4v.x, wb4.x, aB);
            aA = ffma2(e4v.y, wa4.y, aA);  aB = ffma2(e4v.y, wb4.y, aB);

            float2 fa = unpack2(aA), fb = unpack2(aB);
            float sA = fa.x + fa.y;
            float sB = fb.x + fb.y;

            float p = qc.x * kc.x * silu_f(sA);
            p = fmaf(qc.y * kc.y, silu_f(sB), p);

            // 3-level octet butterfly; 4 partials per edge land in smem
            p += __shfl_xor_sync(0xffffffffu, p, 4);
            p += __shfl_xor_sync(0xffffffffu, p, 2);
            p += __shfl_xor_sync(0xffffffffu, p, 1);
            if ((lane & 7) == 0) oct_s[warp][el][lane >> 3] = p;
        }
        __syncwarp();

        // --- finish: lanes 0..15 each close one edge (batched, coalesced)
        if (lane < EPB) {
            const float4 pv = *(const float4*)&oct_s[warp][lane][0];
            float s = (pv.x + pv.y) + (pv.z + pv.w);
            out[(size_t)(e0 + lane) * HEADS + warp] = silu_f(s);
        }
        __syncwarp();
        buf ^= 1;
    }
}

// ---------------------------------------------------------------------------
extern "C" void kernel_launch(void* const* d_in, const int* in_sizes, int n_in,
                              void* d_out, int out_size)
{
    const float* dist = (const float*)d_in[0];
    const int*   nbrs = (const int*)  d_in[1];
    const float* x_i  = (const float*)d_in[2];
    const float* W_q  = (const float*)d_in[3];
    const float* b_q  = (const float*)d_in[4];
    const float* W_k  = (const float*)d_in[5];
    const float* b_k  = (const float*)d_in[6];
    const float* W_dk = (const float*)d_in[7];
    const float* b_dk = (const float*)d_in[8];
    float* out = (float*)d_out;

    dim3 g1((N_NODES + BM - 1) / BM, NCOLS / BN);   // 157 x 8
    qk_gemm_kernel<<<g1, 256>>>(x_i, W_q, b_q, W_k, b_k);

    edge_kernel<<<GRID2, TPB2>>>(dist, nbrs, W_dk, b_dk, out);
}

// round 15
// speedup vs baseline: 1.0822x; 1.0070x over previous
#include <cuda_runtime.h>
#include <cuda_fp16.h>
#include <math.h>

#define N_NODES 20000
#define N_EDGES 150000
#define FEAT    64
#define HEADS   8
#define N_RBF   20
#define HF      512          // HEADS*FEAT
#define NCOLS   1024         // Q(512) | K(512)
#define CUTOFF  5.0f
#define PI_F    3.14159265358979f

// Scratch: per-node Q and K projections, [node][ Q(0..511) | K(512..1023) ]
__device__ float g_QK[(size_t)N_NODES * NCOLS];
// fp16 hi/lo splits (Markidis) of x_i and W = [W_q ; W_k]
__device__ __half g_xhi[(size_t)N_NODES * FEAT];
__device__ __half g_xlo[(size_t)N_NODES * FEAT];
__device__ __half g_whi[(size_t)NCOLS * FEAT];
__device__ __half g_wlo[(size_t)NCOLS * FEAT];

// ---------------------------------------------------------------------------
// Packed f32x2 helpers (Blackwell FFMA2 — only reachable via PTX fma.rn.f32x2)
// ---------------------------------------------------------------------------
__device__ __forceinline__ unsigned long long ffma2(unsigned long long a,
                                                    unsigned long long b,
                                                    unsigned long long c) {
    unsigned long long d;
    asm("fma.rn.f32x2 %0, %1, %2, %3;" : "=l"(d) : "l"(a), "l"(b), "l"(c));
    return d;
}

__device__ __forceinline__ unsigned long long pack2(float lo, float hi) {
    unsigned long long r;
    asm("mov.b64 %0, {%1, %2};" : "=l"(r) : "f"(lo), "f"(hi));
    return r;
}

__device__ __forceinline__ float2 unpack2(unsigned long long v) {
    float2 r;
    asm("mov.b64 {%0, %1}, %2;" : "=f"(r.x), "=f"(r.y) : "l"(v));
    return r;
}

// m16n8k16 f16 MMA, fp32 accumulate
#define MMA16816(C, A, B) \
    asm volatile("mma.sync.aligned.m16n8k16.row.col.f32.f16.f16.f32 " \
        "{%0,%1,%2,%3}, {%4,%5,%6,%7}, {%8,%9}, {%0,%1,%2,%3};" \
        : "+f"((C)[0]), "+f"((C)[1]), "+f"((C)[2]), "+f"((C)[3]) \
        : "r"((A)[0]), "r"((A)[1]), "r"((A)[2]), "r"((A)[3]), \
          "r"((B)[0]), "r"((B)[1]))

// ---------------------------------------------------------------------------
// Kernel 0: split x_i and W into fp16 hi/lo pairs.
// ---------------------------------------------------------------------------
__global__ void prep_kernel(const float* __restrict__ x_i,
                            const float* __restrict__ W_q,
                            const float* __restrict__ W_k)
{
    const int NX = N_NODES * FEAT;       // 1,280,000
    const int NW = NCOLS * FEAT;         // 65,536
    int i = blockIdx.x * 256 + threadIdx.x;
    if (i < NX) {
        float v = x_i[i];
        __half h = __float2half_rn(v);
        g_xhi[i] = h;
        g_xlo[i] = __float2half_rn(v - __half2float(h));
    } else if (i < NX + NW) {
        int j = i - NX;                  // j = c*FEAT + f
        float v = (j < HF * FEAT) ? W_q[j] : W_k[j - HF * FEAT];
        __half h = __float2half_rn(v);
        g_whi[j] = h;
        g_wlo[j] = __float2half_rn(v - __half2float(h));
    }
}

// ---------------------------------------------------------------------------
// Kernel 1: QK projection GEMM via split-fp16 tensor-core MMA (3 MMAs:
// hi*hi + hi*lo + lo*hi -> fp32-class accuracy).
// C[n,c] = sum_f x[n,f]*W[c,f] + b[c].  CTA tile 128x128, warp tile 64x32,
// warps laid out 2(m) x 4(n). B fragments persistent in registers.
// ---------------------------------------------------------------------------
__global__ __launch_bounds__(256)
void qk_mma_kernel(const float* __restrict__ b_q, const float* __restrict__ b_k)
{
    const int lane = threadIdx.x & 31;
    const int warp = threadIdx.x >> 5;
    const int g = lane >> 2;        // 0..7
    const int t = lane & 3;         // 0..3
    const int wm = warp >> 2;       // 0..1  (m block within CTA)
    const int wn = warp & 3;        // 0..3  (n block within CTA)
    const int row_w = blockIdx.x * 128 + wm * 64;
    const int col_w = blockIdx.y * 128 + wn * 32;

    // --- persistent B fragments: b0={B[2t][g],B[2t+1][g]}, b1 same k+8
    //     with B[k][n] = W[n][k] (W rows are k-contiguous)
    unsigned bh[4][4][2], bl[4][4][2];   // [ntile][kstep][b0/b1]
    #pragma unroll
    for (int nt = 0; nt < 4; nt++) {
        int col = col_w + nt * 8 + g;
        const __half* wrh = g_whi + (size_t)col * FEAT;
        const __half* wrl = g_wlo + (size_t)col * FEAT;
        #pragma unroll
        for (int ks = 0; ks < 4; ks++) {
            bh[nt][ks][0] = *(const unsigned*)(wrh + ks * 16 + 2 * t);
            bh[nt][ks][1] = *(const unsigned*)(wrh + ks * 16 + 2 * t + 8);
            bl[nt][ks][0] = *(const unsigned*)(wrl + ks * 16 + 2 * t);
            bl[nt][ks][1] = *(const unsigned*)(wrl + ks * 16 + 2 * t + 8);
        }
    }

    #pragma unroll
    for (int mt = 0; mt < 4; mt++) {
        const int r0 = row_w + mt * 16 + g;
        const int r1 = r0 + 8;
        const int r0c = (r0 < N_NODES) ? r0 : 0;   // clamp loads, predicate stores
        const int r1c = (r1 < N_NODES) ? r1 : 0;
        const __half* x0h = g_xhi + (size_t)r0c * FEAT;
        const __half* x1h = g_xhi + (size_t)r1c * FEAT;
        const __half* x0l = g_xlo + (size_t)r0c * FEAT;
        const __half* x1l = g_xlo + (size_t)r1c * FEAT;

        // A fragments: a0=(g,2t..2t+1), a1=(g+8,2t..), a2=(g,2t+8..), a3=(g+8,2t+8..)
        unsigned ah[4][4], al[4][4];     // [kstep][a0..a3]
        #pragma unroll
        for (int ks = 0; ks < 4; ks++) {
            ah[ks][0] = *(const unsigned*)(x0h + ks * 16 + 2 * t);
            ah[ks][1] = *(const unsigned*)(x1h + ks * 16 + 2 * t);
            ah[ks][2] = *(const unsigned*)(x0h + ks * 16 + 2 * t + 8);
            ah[ks][3] = *(const unsigned*)(x1h + ks * 16 + 2 * t + 8);
            al[ks][0] = *(const unsigned*)(x0l + ks * 16 + 2 * t);
            al[ks][1] = *(const unsigned*)(x1l + ks * 16 + 2 * t);
            al[ks][2] = *(const unsigned*)(x0l + ks * 16 + 2 * t + 8);
            al[ks][3] = *(const unsigned*)(x1l + ks * 16 + 2 * t + 8);
        }

        float c[4][4];
        #pragma unroll
        for (int nt = 0; nt < 4; nt++)
            #pragma unroll
            for (int q = 0; q < 4; q++) c[nt][q] = 0.f;

        #pragma unroll
        for (int ks = 0; ks < 4; ks++)
            #pragma unroll
            for (int nt = 0; nt < 4; nt++) {
                MMA16816(c[nt], ah[ks], bh[nt][ks]);   // hi*hi
                MMA16816(c[nt], ah[ks], bl[nt][ks]);   // hi*lo
                MMA16816(c[nt], al[ks], bh[nt][ks]);   // lo*hi
            }

        // epilogue: C rows g (c0,c1) and g+8 (c2,c3), cols 2t,2t+1 per n-tile
        #pragma unroll
        for (int nt = 0; nt < 4; nt++) {
            int cg = col_w + nt * 8 + 2 * t;
            float2 bb = (cg < HF) ? *(const float2*)(b_q + cg)
                                  : *(const float2*)(b_k + (cg - HF));
            if (r0 < N_NODES)
                *(float2*)&g_QK[(size_t)r0 * NCOLS + cg] =
                    make_float2(c[nt][0] + bb.x, c[nt][1] + bb.y);
            if (r1 < N_NODES)
                *(float2*)&g_QK[(size_t)r1 * NCOLS + cg] =
                    make_float2(c[nt][2] + bb.x, c[nt][3] + bb.y);
        }
    }
}

// ---------------------------------------------------------------------------
// Kernel 2: fused edge kernel (R9/R11 measured-best, byte-identical).
// 256 threads, warp == head, 2 cols/thread, depth-2 q/k prefetch, separate
// silus, 3-level octet butterfly + smem partials, batched finish per group.
// ---------------------------------------------------------------------------
#define EPB 16                    // edges per block iteration
#define NGROUPS (N_EDGES / EPB)   // 9375, exact
#define GRID2   444               // 148 SMs * 3 CTAs
#define TPB2    256

__device__ __forceinline__ float silu_f(float x) {
    return __fdividef(x, 1.f + __expf(-x));
}

__global__ __launch_bounds__(TPB2, 3)
void edge_kernel(const float* __restrict__ dist,
                 const int*   __restrict__ nbrs,
                 const float* __restrict__ W_dk,
                 const float* __restrict__ b_dk,
                 float*       __restrict__ out)
{
    __shared__ alignas(16) float ef_s[2][EPB][24];   // 20 RBF values, padded row
    __shared__ int2 idx_s[2][EPB];
    __shared__ alignas(16) float oct_s[HEADS][EPB][4];  // octet partials per warp

    const int tid  = threadIdx.x;
    const int lane = tid & 31;
    const int warp = tid >> 5;           // == head
    const int c0   = warp * 64 + lane * 2;

    // Base pointers with the column offset folded in once
    const float* __restrict__ gQ = g_QK + c0;
    const float* __restrict__ gK = g_QK + HF + c0;

    // W_dk rows for cols c0 and c0+1 (each 20 floats, 80B => 16B aligned),
    // as r-packed f32x2 pairs: 10 pairs per column.
    const ulonglong2* wpA = (const ulonglong2*)(W_dk + (size_t)c0 * N_RBF);
    const ulonglong2* wpB = (const ulonglong2*)(W_dk + (size_t)(c0 + 1) * N_RBF);
    const ulonglong2 wa0 = wpA[0], wa1 = wpA[1], wa2 = wpA[2], wa3 = wpA[3], wa4 = wpA[4];
    const ulonglong2 wb0 = wpB[0], wb1 = wpB[1], wb2 = wpB[2], wb3 = wpB[3], wb4 = wpB[4];
    const unsigned long long aA0 = pack2(b_dk[c0], 0.f);
    const unsigned long long aB0 = pack2(b_dk[c0 + 1], 0.f);
    const unsigned long long zz  = pack2(0.f, 0.f);

    // stage-1 fill for group g into buffer buf
    auto fill = [&](int g, int buf) {
        const int e0 = g * EPB;
        #pragma unroll
        for (int v = tid; v < EPB * N_RBF; v += TPB2) {
            int el = v / N_RBF, r = v % N_RBF;
            float d   = dist[e0 + el];
            float t   = PI_F * d * (1.0f / CUTOFF);
            float env = (d < CUTOFF) ? 0.5f * (__cosf(t) + 1.f) : 0.f;
            ef_s[buf][el][r] = __sinf((float)(r + 1) * t) * __fdividef(env, d);
        }
        if (tid < EPB)
            idx_s[buf][tid] = ((const int2*)nbrs)[e0 + tid];
    };

    int g = blockIdx.x;
    fill(g, 0);
    int buf = 0;

    for (; g < NGROUPS; g += GRID2) {
        __syncthreads();                 // buf ready for everyone
        const int gn = g + GRID2;
        if (gn < NGROUPS) fill(gn, buf ^ 1);   // prefetch next group's RBF

        const int e0 = g * EPB;

        // --- depth-2 pipeline: q/k for edge el+1 loads while edge el computes
        int2 nn = idx_s[buf][0];
        float2 q = *(const float2*)(gQ + (size_t)nn.x * NCOLS);
        float2 k = *(const float2*)(gK + (size_t)nn.y * NCOLS);

        #pragma unroll 4
        for (int el = 0; el < EPB; el++) {
            float2 qc = q, kc = k;
            if (el + 1 < EPB) {
                int2 nn1 = idx_s[buf][el + 1];
                q = *(const float2*)(gQ + (size_t)nn1.x * NCOLS);
                k = *(const float2*)(gK + (size_t)nn1.y * NCOLS);
            }

            const ulonglong2* efp = (const ulonglong2*)&ef_s[buf][el][0];
            ulonglong2 e0v = efp[0], e1v = efp[1], e2v = efp[2], e3v = efp[3], e4v = efp[4];

            unsigned long long aA1 = aA0, aA2 = zz;   // column c0
            unsigned long long aB1 = aB0, aB2 = zz;   // column c0+1
            aA1 = ffma2(e0v.x, wa0.x, aA1);  aA2 = ffma2(e0v.y, wa0.y, aA2);
            aB1 = ffma2(e0v.x, wb0.x, aB1);  aB2 = ffma2(e0v.y, wb0.y, aB2);
            aA1 = ffma2(e1v.x, wa1.x, aA1);  aA2 = ffma2(e1v.y, wa1.y, aA2);
            aB1 = ffma2(e1v.x, wb1.x, aB1);  aB2 = ffma2(e1v.y, wb1.y, aB2);
            aA1 = ffma2(e2v.x, wa2.x, aA1);  aA2 = ffma2(e2v.y, wa2.y, aA2);
            aB1 = ffma2(e2v.x, wb2.x, aB1);  aB2 = ffma2(e2v.y, wb2.y, aB2);
            aA1 = ffma2(e3v.x, wa3.x, aA1);  aA2 = ffma2(e3v.y, wa3.y, aA2);
            aB1 = ffma2(e3v.x, wb3.x, aB1);  aB2 = ffma2(e3v.y, wb3.y, aB2);
            aA1 = ffma2(e4v.x, wa4.x, aA1);  aA2 = ffma2(e4v.y, wa4.y, aA2);
            aB1 = ffma2(e4v.x, wb4.x, aB1);  aB2 = ffma2(e4v.y, wb4.y, aB2);

            float2 fa1 = unpack2(aA1), fa2 = unpack2(aA2);
            float2 fb1 = unpack2(aB1), fb2 = unpack2(aB2);
            float sA = (fa1.x + fa1.y) + (fa2.x + fa2.y);
            float sB = (fb1.x + fb1.y) + (fb2.x + fb2.y);

            float p = qc.x * kc.x * silu_f(sA);
            p = fmaf(qc.y * kc.y, silu_f(sB), p);

            // 3-level octet butterfly; 4 partials per edge land in smem
            p += __shfl_xor_sync(0xffffffffu, p, 4);
            p += __shfl_xor_sync(0xffffffffu, p, 2);
            p += __shfl_xor_sync(0xffffffffu, p, 1);
            if ((lane & 7) == 0) oct_s[warp][el][lane >> 3] = p;
        }
        __syncwarp();

        // --- finish: lanes 0..15 each close one edge (batched, coalesced)
        if (lane < EPB) {
            const float4 pv = *(const float4*)&oct_s[warp][lane][0];
            float s = (pv.x + pv.y) + (pv.z + pv.w);
            out[(size_t)(e0 + lane) * HEADS + warp] = silu_f(s);
        }
        __syncwarp();
        buf ^= 1;
    }
}

// ---------------------------------------------------------------------------
extern "C" void kernel_launch(void* const* d_in, const int* in_sizes, int n_in,
                              void* d_out, int out_size)
{
    const float* dist = (const float*)d_in[0];
    const int*   nbrs = (const int*)  d_in[1];
    const float* x_i  = (const float*)d_in[2];
    const float* W_q  = (const float*)d_in[3];
    const float* b_q  = (const float*)d_in[4];
    const float* W_k  = (const float*)d_in[5];
    const float* b_k  = (const float*)d_in[6];
    const float* W_dk = (const float*)d_in[7];
    const float* b_dk = (const float*)d_in[8];
    float* out = (float*)d_out;

    const int NX = N_NODES * FEAT, NW = NCOLS * FEAT;
    prep_kernel<<<(NX + NW + 255) / 256, 256>>>(x_i, W_q, W_k);

    dim3 g1((N_NODES + 127) / 128, NCOLS / 128);    // 157 x 8
    qk_mma_kernel<<<g1, 256>>>(b_q, b_k);

    edge_kernel<<<GRID2, TPB2>>>(dist, nbrs, W_dk, b_dk, out);
}

// round 17
// speedup vs baseline: 1.2497x; 1.1548x over previous
#include <cuda_runtime.h>
#include <cuda_fp16.h>
#include <math.h>

#define N_NODES 20000
#define N_EDGES 150000
#define FEAT    64
#define HEADS   8
#define N_RBF   20
#define HF      512          // HEADS*FEAT
#define NCOLS   1024         // Q(512) | K(512)
#define CUTOFF  5.0f
#define PI_F    3.14159265358979f

// Scratch: per-node Q and K projections, [node][ Q(0..511) | K(512..1023) ]
__device__ float g_QK[(size_t)N_NODES * NCOLS];
// fp16 hi/lo splits (Markidis) of x_i and W = [W_q ; W_k]
__device__ __half g_xhi[(size_t)N_NODES * FEAT];
__device__ __half g_xlo[(size_t)N_NODES * FEAT];
__device__ __half g_whi[(size_t)NCOLS * FEAT];
__device__ __half g_wlo[(size_t)NCOLS * FEAT];

// ---------------------------------------------------------------------------
// Packed f32x2 helpers (Blackwell FFMA2 — only reachable via PTX fma.rn.f32x2)
// ---------------------------------------------------------------------------
__device__ __forceinline__ unsigned long long ffma2(unsigned long long a,
                                                    unsigned long long b,
                                                    unsigned long long c) {
    unsigned long long d;
    asm("fma.rn.f32x2 %0, %1, %2, %3;" : "=l"(d) : "l"(a), "l"(b), "l"(c));
    return d;
}

__device__ __forceinline__ unsigned long long pack2(float lo, float hi) {
    unsigned long long r;
    asm("mov.b64 %0, {%1, %2};" : "=l"(r) : "f"(lo), "f"(hi));
    return r;
}

__device__ __forceinline__ float2 unpack2(unsigned long long v) {
    float2 r;
    asm("mov.b64 {%0, %1}, %2;" : "=f"(r.x), "=f"(r.y) : "l"(v));
    return r;
}

// m16n8k16 f16 MMA, fp32 accumulate
#define MMA16816(C, A, B) \
    asm volatile("mma.sync.aligned.m16n8k16.row.col.f32.f16.f16.f32 " \
        "{%0,%1,%2,%3}, {%4,%5,%6,%7}, {%8,%9}, {%0,%1,%2,%3};" \
        : "+f"((C)[0]), "+f"((C)[1]), "+f"((C)[2]), "+f"((C)[3]) \
        : "r"((A)[0]), "r"((A)[1]), "r"((A)[2]), "r"((A)[3]), \
          "r"((B)[0]), "r"((B)[1]))

// ---------------------------------------------------------------------------
// Kernel 0: split x_i and W into fp16 hi/lo pairs (vectorized).
// ---------------------------------------------------------------------------
__global__ __launch_bounds__(256)
void prep_kernel(const float* __restrict__ x_i,
                 const float* __restrict__ W_q,
                 const float* __restrict__ W_k)
{
    const int NX4 = N_NODES * FEAT / 4;   // 320000
    const int NW4 = NCOLS * FEAT / 4;     // 16384
    int i = blockIdx.x * 256 + threadIdx.x;
    float4 v;
    __half2 *dh, *dl;
    if (i < NX4) {
        v  = ((const float4*)x_i)[i];
        dh = (__half2*)g_xhi + 2 * (size_t)i;
        dl = (__half2*)g_xlo + 2 * (size_t)i;
    } else if (i < NX4 + NW4) {
        int j = i - NX4;
        v  = (j < HF * FEAT / 4) ? ((const float4*)W_q)[j]
                                 : ((const float4*)W_k)[j - HF * FEAT / 4];
        dh = (__half2*)g_whi + 2 * (size_t)j;
        dl = (__half2*)g_wlo + 2 * (size_t)j;
    } else return;
    __half2 h0 = __floats2half2_rn(v.x, v.y);
    __half2 h1 = __floats2half2_rn(v.z, v.w);
    float2  f0 = __half22float2(h0);
    float2  f1 = __half22float2(h1);
    dh[0] = h0;
    dh[1] = h1;
    dl[0] = __floats2half2_rn(v.x - f0.x, v.y - f0.y);
    dl[1] = __floats2half2_rn(v.z - f1.x, v.w - f1.y);
}

// ---------------------------------------------------------------------------
// Kernel 1: QK projection GEMM via split-fp16 tensor-core MMA,
// smem-staged tiles (coalesced gmem, conflict-free fragment reads).
// CTA tile 128x128, warp tile 64x32 (warps 2m x 4n), K=64 as 2 chunks of 32
// (keeps static smem at 40 KB < 48 KB limit). Accumulators persist across
// chunks; Markidis 3-MMA split for fp32-class accuracy.
// ---------------------------------------------------------------------------
#define SPAD 40   // smem row stride (halves): bank (20g+8ks+t)%32 all distinct

__global__ __launch_bounds__(256)
void qk_mma_kernel(const float* __restrict__ b_q, const float* __restrict__ b_k)
{
    __shared__ __half As_h[128][SPAD], As_l[128][SPAD];
    __shared__ __half Bs_h[128][SPAD], Bs_l[128][SPAD];

    const int tid  = threadIdx.x;
    const int lane = tid & 31;
    const int warp = tid >> 5;
    const int g = lane >> 2;        // 0..7
    const int t = lane & 3;         // 0..3
    const int wm = warp >> 2;       // 0..1
    const int wn = warp & 3;        // 0..3
    const int row0 = blockIdx.x * 128;
    const int col0 = blockIdx.y * 128;

    // accumulators: [mt][nt][quad], persist across the 2 k-chunks
    float c[4][4][4];
    #pragma unroll
    for (int mt = 0; mt < 4; mt++)
        #pragma unroll
        for (int nt = 0; nt < 4; nt++)
            #pragma unroll
            for (int q = 0; q < 4; q++) c[mt][nt][q] = 0.f;

    #pragma unroll
    for (int kc = 0; kc < 2; kc++) {
        const int kh = kc * 32;           // k offset in halves

        // --- coalesced staging: 128 rows x 4 float4-chunks per array
        #pragma unroll
        for (int r = 0; r < 2; r++) {
            int chunk = tid + 256 * r;    // 0..511
            int row = chunk >> 2, cc = chunk & 3;
            int m = row0 + row;
            float4 vah = make_float4(0.f, 0.f, 0.f, 0.f), val = vah;
            if (m < N_NODES) {
                vah = *(const float4*)(g_xhi + (size_t)m * FEAT + kh + cc * 8);
                val = *(const float4*)(g_xlo + (size_t)m * FEAT + kh + cc * 8);
            }
            *(float4*)&As_h[row][cc * 8] = vah;
            *(float4*)&As_l[row][cc * 8] = val;
            int col = col0 + row;         // always < NCOLS
            *(float4*)&Bs_h[row][cc * 8] =
                *(const float4*)(g_whi + (size_t)col * FEAT + kh + cc * 8);
            *(float4*)&Bs_l[row][cc * 8] =
                *(const float4*)(g_wlo + (size_t)col * FEAT + kh + cc * 8);
        }
        __syncthreads();

        // --- B fragments for this chunk (2 k16-steps)
        unsigned bh[4][2][2], bl[4][2][2];   // [ntile][kstep][b0/b1]
        #pragma unroll
        for (int nt = 0; nt < 4; nt++) {
            int cl = wn * 32 + nt * 8 + g;
            #pragma unroll
            for (int ks = 0; ks < 2; ks++) {
                bh[nt][ks][0] = *(const unsigned*)&Bs_h[cl][ks * 16 + 2 * t];
                bh[nt][ks][1] = *(const unsigned*)&Bs_h[cl][ks * 16 + 2 * t + 8];
                bl[nt][ks][0] = *(const unsigned*)&Bs_l[cl][ks * 16 + 2 * t];
                bl[nt][ks][1] = *(const unsigned*)&Bs_l[cl][ks * 16 + 2 * t + 8];
            }
        }

        #pragma unroll
        for (int mt = 0; mt < 4; mt++) {
            const int rl0 = wm * 64 + mt * 16 + g;
            const int rl1 = rl0 + 8;

            unsigned ah[2][4], al[2][4];     // [kstep][a0..a3]
            #pragma unroll
            for (int ks = 0; ks < 2; ks++) {
                ah[ks][0] = *(const unsigned*)&As_h[rl0][ks * 16 + 2 * t];
                ah[ks][1] = *(const unsigned*)&As_h[rl1][ks * 16 + 2 * t];
                ah[ks][2] = *(const unsigned*)&As_h[rl0][ks * 16 + 2 * t + 8];
                ah[ks][3] = *(const unsigned*)&As_h[rl1][ks * 16 + 2 * t + 8];
                al[ks][0] = *(const unsigned*)&As_l[rl0][ks * 16 + 2 * t];
                al[ks][1] = *(const unsigned*)&As_l[rl1][ks * 16 + 2 * t];
                al[ks][2] = *(const unsigned*)&As_l[rl0][ks * 16 + 2 * t + 8];
                al[ks][3] = *(const unsigned*)&As_l[rl1][ks * 16 + 2 * t + 8];
            }

            #pragma unroll
            for (int ks = 0; ks < 2; ks++)
                #pragma unroll
                for (int nt = 0; nt < 4; nt++) {
                    MMA16816(c[mt][nt], ah[ks], bh[nt][ks]);   // hi*hi
                    MMA16816(c[mt][nt], ah[ks], bl[nt][ks]);   // hi*lo
                    MMA16816(c[mt][nt], al[ks], bh[nt][ks]);   // lo*hi
                }
        }
        __syncthreads();   // tiles free for next chunk's staging
    }

    // --- epilogue: rows r0 (c0,c1) and r0+8 (c2,c3), cols 2t,2t+1 per n-tile
    #pragma unroll
    for (int mt = 0; mt < 4; mt++) {
        const int r0 = row0 + wm * 64 + mt * 16 + g;
        const int r1 = r0 + 8;
        #pragma unroll
        for (int nt = 0; nt < 4; nt++) {
            int cg = col0 + wn * 32 + nt * 8 + 2 * t;
            float2 bb = (cg < HF) ? *(const float2*)(b_q + cg)
                                  : *(const float2*)(b_k + (cg - HF));
            if (r0 < N_NODES)
                *(float2*)&g_QK[(size_t)r0 * NCOLS + cg] =
                    make_float2(c[mt][nt][0] + bb.x, c[mt][nt][1] + bb.y);
            if (r1 < N_NODES)
                *(float2*)&g_QK[(size_t)r1 * NCOLS + cg] =
                    make_float2(c[mt][nt][2] + bb.x, c[mt][nt][3] + bb.y);
        }
    }
}

// ---------------------------------------------------------------------------
// Kernel 2: fused edge kernel (R9/R11 measured-best, byte-identical).
// ---------------------------------------------------------------------------
#define EPB 16                    // edges per block iteration
#define NGROUPS (N_EDGES / EPB)   // 9375, exact
#define GRID2   444               // 148 SMs * 3 CTAs
#define TPB2    256

__device__ __forceinline__ float silu_f(float x) {
    return __fdividef(x, 1.f + __expf(-x));
}

__global__ __launch_bounds__(TPB2, 3)
void edge_kernel(const float* __restrict__ dist,
                 const int*   __restrict__ nbrs,
                 const float* __restrict__ W_dk,
                 const float* __restrict__ b_dk,
                 float*       __restrict__ out)
{
    __shared__ alignas(16) float ef_s[2][EPB][24];   // 20 RBF values, padded row
    __shared__ int2 idx_s[2][EPB];
    __shared__ alignas(16) float oct_s[HEADS][EPB][4];  // octet partials per warp

    const int tid  = threadIdx.x;
    const int lane = tid & 31;
    const int warp = tid >> 5;           // == head
    const int c0   = warp * 64 + lane * 2;

    const float* __restrict__ gQ = g_QK + c0;
    const float* __restrict__ gK = g_QK + HF + c0;

    const ulonglong2* wpA = (const ulonglong2*)(W_dk + (size_t)c0 * N_RBF);
    const ulonglong2* wpB = (const ulonglong2*)(W_dk + (size_t)(c0 + 1) * N_RBF);
    const ulonglong2 wa0 = wpA[0], wa1 = wpA[1], wa2 = wpA[2], wa3 = wpA[3], wa4 = wpA[4];
    const ulonglong2 wb0 = wpB[0], wb1 = wpB[1], wb2 = wpB[2], wb3 = wpB[3], wb4 = wpB[4];
    const unsigned long long aA0 = pack2(b_dk[c0], 0.f);
    const unsigned long long aB0 = pack2(b_dk[c0 + 1], 0.f);
    const unsigned long long zz  = pack2(0.f, 0.f);

    auto fill = [&](int g, int buf) {
        const int e0 = g * EPB;
        #pragma unroll
        for (int v = tid; v < EPB * N_RBF; v += TPB2) {
            int el = v / N_RBF, r = v % N_RBF;
            float d   = dist[e0 + el];
            float t   = PI_F * d * (1.0f / CUTOFF);
            float env = (d < CUTOFF) ? 0.5f * (__cosf(t) + 1.f) : 0.f;
            ef_s[buf][el][r] = __sinf((float)(r + 1) * t) * __fdividef(env, d);
        }
        if (tid < EPB)
            idx_s[buf][tid] = ((const int2*)nbrs)[e0 + tid];
    };

    int g = blockIdx.x;
    fill(g, 0);
    int buf = 0;

    for (; g < NGROUPS; g += GRID2) {
        __syncthreads();
        const int gn = g + GRID2;
        if (gn < NGROUPS) fill(gn, buf ^ 1);

        const int e0 = g * EPB;

        int2 nn = idx_s[buf][0];
        float2 q = *(const float2*)(gQ + (size_t)nn.x * NCOLS);
        float2 k = *(const float2*)(gK + (size_t)nn.y * NCOLS);

        #pragma unroll 4
        for (int el = 0; el < EPB; el++) {
            float2 qc = q, kc = k;
            if (el + 1 < EPB) {
                int2 nn1 = idx_s[buf][el + 1];
                q = *(const float2*)(gQ + (size_t)nn1.x * NCOLS);
                k = *(const float2*)(gK + (size_t)nn1.y * NCOLS);
            }

            const ulonglong2* efp = (const ulonglong2*)&ef_s[buf][el][0];
            ulonglong2 e0v = efp[0], e1v = efp[1], e2v = efp[2], e3v = efp[3], e4v = efp[4];

            unsigned long long aA1 = aA0, aA2 = zz;
            unsigned long long aB1 = aB0, aB2 = zz;
            aA1 = ffma2(e0v.x, wa0.x, aA1);  aA2 = ffma2(e0v.y, wa0.y, aA2);
            aB1 = ffma2(e0v.x, wb0.x, aB1);  aB2 = ffma2(e0v.y, wb0.y, aB2);
            aA1 = ffma2(e1v.x, wa1.x, aA1);  aA2 = ffma2(e1v.y, wa1.y, aA2);
            aB1 = ffma2(e1v.x, wb1.x, aB1);  aB2 = ffma2(e1v.y, wb1.y, aB2);
            aA1 = ffma2(e2v.x, wa2.x, aA1);  aA2 = ffma2(e2v.y, wa2.y, aA2);
            aB1 = ffma2(e2v.x, wb2.x, aB1);  aB2 = ffma2(e2v.y, wb2.y, aB2);
            aA1 = ffma2(e3v.x, wa3.x, aA1);  aA2 = ffma2(e3v.y, wa3.y, aA2);
            aB1 = ffma2(e3v.x, wb3.x, aB1);  aB2 = ffma2(e3v.y, wb3.y, aB2);
            aA1 = ffma2(e4v.x, wa4.x, aA1);  aA2 = ffma2(e4v.y, wa4.y, aA2);
            aB1 = ffma2(e4v.x, wb4.x, aB1);  aB2 = ffma2(e4v.y, wb4.y, aB2);

            float2 fa1 = unpack2(aA1), fa2 = unpack2(aA2);
            float2 fb1 = unpack2(aB1), fb2 = unpack2(aB2);
            float sA = (fa1.x + fa1.y) + (fa2.x + fa2.y);
            float sB = (fb1.x + fb1.y) + (fb2.x + fb2.y);

            float p = qc.x * kc.x * silu_f(sA);
            p = fmaf(qc.y * kc.y, silu_f(sB), p);

            p += __shfl_xor_sync(0xffffffffu, p, 4);
            p += __shfl_xor_sync(0xffffffffu, p, 2);
            p += __shfl_xor_sync(0xffffffffu, p, 1);
            if ((lane & 7) == 0) oct_s[warp][el][lane >> 3] = p;
        }
        __syncwarp();

        if (lane < EPB) {
            const float4 pv = *(const float4*)&oct_s[warp][lane][0];
            float s = (pv.x + pv.y) + (pv.z + pv.w);
            out[(size_t)(e0 + lane) * HEADS + warp] = silu_f(s);
        }
        __syncwarp();
        buf ^= 1;
    }
}

// ---------------------------------------------------------------------------
extern "C" void kernel_launch(void* const* d_in, const int* in_sizes, int n_in,
                              void* d_out, int out_size)
{
    const float* dist = (const float*)d_in[0];
    const int*   nbrs = (const int*)  d_in[1];
    const float* x_i  = (const float*)d_in[2];
    const float* W_q  = (const float*)d_in[3];
    const float* b_q  = (const float*)d_in[4];
    const float* W_k  = (const float*)d_in[5];
    const float* b_k  = (const float*)d_in[6];
    const float* W_dk = (const float*)d_in[7];
    const float* b_dk = (const float*)d_in[8];
    float* out = (float*)d_out;

    const int NV4 = N_NODES * FEAT / 4 + NCOLS * FEAT / 4;
    prep_kernel<<<(NV4 + 255) / 256, 256>>>(x_i, W_q, W_k);

    dim3 g1((N_NODES + 127) / 128, NCOLS / 128);    // 157 x 8
    qk_mma_kernel<<<g1, 256>>>(b_q, b_k);

    edge_kernel<<<GRID2, TPB2>>>(dist, nbrs, W_dk, b_dk, out);
}